// round 10
// baseline (speedup 1.0000x reference)
#include <cuda_runtime.h>
#include <cstdint>

typedef unsigned long long ull;

#define EMB 128
#define INT_EMB 64
#define NRAD 6
#define NSR 42
#define BASIS 8
#define E_EDGES 262144
#define T_TRIP 2097152

// ---------------- scratch (device globals) ------------------------------------
__device__ float g_Wr[NRAD*EMB];
__device__ float g_xji[(size_t)E_EDGES*EMB];
__device__ float g_upd[(size_t)E_EDGES*EMB];
__device__ float g_xkj2[(size_t)E_EDGES*INT_EMB];
__device__ float g_agg[(size_t)E_EDGES*INT_EMB];
__device__ uint32_t g_Bf[163840];   // all weights, tf32 fragment layout

// B-frag offsets (u32 elements)
#define OFF_JI   0
#define OFF_KJ   16384
#define OFF_DOWN 32768
#define OFF_UP   40960
#define OFF_B1   49152
#define OFF_B2   65536
#define OFF_FIN  81920
#define OFF_A10  98304
#define OFF_A20  114688
#define OFF_A11  131072
#define OFF_A21  147456

// ---------------- helpers ------------------------------------------------------
__device__ __forceinline__ float silu_f(float x){ return x * (1.0f/(1.0f + __expf(-x))); }
__device__ __forceinline__ uint32_t to_tf32(float f){
    uint32_t u; asm("cvt.rna.tf32.f32 %0, %1;" : "=r"(u) : "f"(f)); return u;
}
__device__ __forceinline__ void mma_tf32(float* c, const uint32_t* a, const uint32_t* b){
    asm volatile("mma.sync.aligned.m16n8k8.row.col.f32.tf32.tf32.f32 "
        "{%0,%1,%2,%3}, {%4,%5,%6,%7}, {%8,%9}, {%0,%1,%2,%3};"
        : "+f"(c[0]), "+f"(c[1]), "+f"(c[2]), "+f"(c[3])
        : "r"(a[0]), "r"(a[1]), "r"(a[2]), "r"(a[3]), "r"(b[0]), "r"(b[1]));
}

// ---------------- K0: fuse W_rbf1 @ W_rbf2 -> g_Wr ----------------------------
__global__ void fuse_wr_kernel(const float* __restrict__ W1, const float* __restrict__ W2) {
    int i = blockIdx.x * blockDim.x + threadIdx.x;
    if (i < NRAD * EMB) {
        int r = i / EMB, n = i % EMB;
        float s = 0.f;
#pragma unroll
        for (int b = 0; b < BASIS; b++) s += W1[r*BASIS + b] * W2[b*EMB + n];
        g_Wr[i] = s;
    }
}

// ---------------- zero g_agg --------------------------------------------------
__global__ void zero_agg_kernel() {
    size_t i = (size_t)blockIdx.x * blockDim.x + threadIdx.x;
    float4 z = {0.f, 0.f, 0.f, 0.f};
    ((float4*)g_agg)[i] = z;
}

// ---------------- B fragment precompute ----------------------------------------
__global__ void stage_Bg(const float* __restrict__ W, uint32_t* __restrict__ out,
                         int K, int N) {
    int i = blockIdx.x * 128 + threadIdx.x;
    int total = K * (N/4);
    if (i >= total) return;
    int k = i / (N/4), n = (i % (N/4)) * 4;
    const float4 b4 = *(const float4*)&W[(size_t)k*N + n];
    float v[4] = {b4.x, b4.y, b4.z, b4.w};
    int NT = N/8;
    int s = k >> 3, kk = k & 7, rg = kk >> 2;
#pragma unroll
    for (int e = 0; e < 4; e++) {
        int nn = (n+e) & 7, nt = (n+e) >> 3;
        int ln = (nn << 2) | (kk & 3);
        out[((s*NT + nt)*32 + ln)*2 + rg] = to_tf32(v[e]);
    }
}

// ---------------- A staging: row-major, XOR-swizzled, tf32 --------------------
template<int K>
__device__ __forceinline__ void stage_A(const float* __restrict__ A, size_t m0,
                                        uint32_t* __restrict__ As, int tid) {
    constexpr int QPR = K/4;
    for (int i = tid; i < 128*QPR; i += 256) {
        int row = i / QPR, q = i % QPR;
        const float4 a4 = *(const float4*)&A[(m0+row)*K + q*4];
        uint4 t;
        t.x = to_tf32(a4.x); t.y = to_tf32(a4.y); t.z = to_tf32(a4.z); t.w = to_tf32(a4.w);
        int c = (q*4) ^ ((row & 7) << 2);
        *(uint4*)&As[row*K + c] = t;
    }
}

// ---------------- shared mainloop: acc[2*WNT][4] += As(K) @ Bf -----------------
template<int K, int NT, int WNT>
__device__ __forceinline__ void run_mma(const uint32_t* __restrict__ As,
                                        const uint32_t* __restrict__ Bf,
                                        int mp, int nt0, int lane,
                                        float (*acc)[4]) {
    const int q = lane >> 2, sw = q << 2;
    const int rowA0 = (mp*32 + q) * K;
    const int rowA1 = (mp*32 + 16 + q) * K;
#pragma unroll
    for (int s = 0; s < K/8; s++) {
        const int c0 = s*8 + (lane & 3);
        uint32_t a0[4], a1[4];
        a0[0] = As[rowA0       + (c0 ^ sw)];
        a0[1] = As[rowA0 + 8*K + (c0 ^ sw)];
        a0[2] = As[rowA0       + ((c0+4) ^ sw)];
        a0[3] = As[rowA0 + 8*K + ((c0+4) ^ sw)];
        a1[0] = As[rowA1       + (c0 ^ sw)];
        a1[1] = As[rowA1 + 8*K + (c0 ^ sw)];
        a1[2] = As[rowA1       + ((c0+4) ^ sw)];
        a1[3] = As[rowA1 + 8*K + ((c0+4) ^ sw)];
#pragma unroll
        for (int j = 0; j < WNT; j++) {
            uint2 b = *(const uint2*)&Bf[((s*NT + nt0 + j)*32 + lane)*2];
            mma_tf32(acc[j],      a0, (const uint32_t*)&b);
            mma_tf32(acc[WNT+j],  a1, (const uint32_t*)&b);
        }
    }
}
template<int W4>
__device__ __forceinline__ void zero_acc(float (*acc)[4]) {
#pragma unroll
    for (int i = 0; i < W4; i++)
#pragma unroll
        for (int e = 0; e < 4; e++) acc[i][e] = 0.f;
}

// ---------------- HEAD: x_ji, x_kj2 in one kernel ------------------------------
__global__ __launch_bounds__(256, 2)
void head_kernel(const float* __restrict__ m, const float* __restrict__ rbf,
                 const uint32_t* __restrict__ Bf,
                 const float* __restrict__ b_ji, const float* __restrict__ b_kj) {
    extern __shared__ __align__(16) uint32_t As[];   // 128*128 u32
    __shared__ float s_Wr[NRAD*EMB];

    const int tid = threadIdx.x, lane = tid & 31, w = tid >> 5;
    const size_t m0 = (size_t)blockIdx.x * 128;
    const int mp = w >> 1, half = w & 1;
    const int q = lane >> 2, sw = q << 2;

    for (int i = tid; i < NRAD*EMB; i += 256) s_Wr[i] = g_Wr[i];
    stage_A<128>(m, m0, As, tid);
    __syncthreads();

    float acc[16][4];

    // ---- GEMM ji: x_ji = silu(m @ W_ji + b_ji) -> gmem ----
    zero_acc<16>(acc);
    run_mma<128,16,8>(As, Bf + OFF_JI, mp, half*8, lane, acc);
#pragma unroll
    for (int i = 0; i < 2; i++) {
        const size_t r_lo = m0 + mp*32 + i*16 + q, r_hi = r_lo + 8;
#pragma unroll
        for (int j = 0; j < 8; j++) {
            const int col = (half*8 + j)*8 + (lane & 3)*2;
            const float2 bj = *(const float2*)&b_ji[col];
            float2 o0, o1;
            o0.x = silu_f(acc[j][0] + bj.x);    o0.y = silu_f(acc[j][1] + bj.y);
            o1.x = silu_f(acc[8+j][2-2] + 0.f), o1.x = silu_f(acc[8+j][2] + bj.x); // placeholder fix below
            o1.x = silu_f(acc[8+j][2] + bj.x);  o1.y = silu_f(acc[8+j][3] + bj.y);
            // NOTE: acc layout: [j] rows (lo16): elems 0,1 = r_lo; 2,3 = r_lo+8? No:
            // m16n8k8 acc: {c0,c1}=row q, {c2,c3}=row q+8 within the 16-row tile.
            o0.x = silu_f(acc[i*8 + j][0] + bj.x);
            o0.y = silu_f(acc[i*8 + j][1] + bj.y);
            o1.x = silu_f(acc[i*8 + j][2] + bj.x);
            o1.y = silu_f(acc[i*8 + j][3] + bj.y);
            *(float2*)&g_xji[r_lo*128 + col] = o0;
            *(float2*)&g_xji[r_hi*128 + col] = o1;
        }
    }

    // ---- GEMM kj: h = silu(m @ W_kj + b_kj) * rbf_env -> As ----
    zero_acc<16>(acc);
    run_mma<128,16,8>(As, Bf + OFF_KJ, mp, half*8, lane, acc);
    __syncthreads();   // all warps done reading As
#pragma unroll
    for (int i = 0; i < 2; i++) {
        const size_t r_lo = m0 + mp*32 + i*16 + q, r_hi = r_lo + 8;
        const int rl = mp*32 + i*16 + q;
        float r6lo[NRAD], r6hi[NRAD];
#pragma unroll
        for (int l = 0; l < NRAD; l++) { r6lo[l] = rbf[r_lo*NRAD + l]; r6hi[l] = rbf[r_hi*NRAD + l]; }
#pragma unroll
        for (int j = 0; j < 8; j++) {
            const int cj = (half*8 + j)*8 + (lane & 3)*2;
            const float2 bj = *(const float2*)&b_kj[cj];
            float e00=0.f,e01=0.f,e10=0.f,e11=0.f;
#pragma unroll
            for (int l = 0; l < NRAD; l++) {
                const float w0 = s_Wr[l*EMB + cj], w1 = s_Wr[l*EMB + cj + 1];
                e00 += r6lo[l]*w0; e01 += r6lo[l]*w1;
                e10 += r6hi[l]*w0; e11 += r6hi[l]*w1;
            }
            float v[4];
            v[0] = silu_f(acc[i*8+j][0] + bj.x) * e00;
            v[1] = silu_f(acc[i*8+j][1] + bj.y) * e01;
            v[2] = silu_f(acc[i*8+j][2] + bj.x) * e10;
            v[3] = silu_f(acc[i*8+j][3] + bj.y) * e11;
#pragma unroll
            for (int e = 0; e < 4; e++) {
                const int r = rl + ((e >> 1) ? 8 : 0);
                const int c = cj + (e & 1);
                As[r*128 + (c ^ sw)] = to_tf32(v[e]);
            }
        }
    }
    __syncthreads();

    // ---- GEMM down: x_kj2 = silu(h @ W_down) -> gmem (N=64) ----
    zero_acc<8>(acc);
    run_mma<128,8,4>(As, Bf + OFF_DOWN, mp, half*4, lane, acc);
#pragma unroll
    for (int i = 0; i < 2; i++) {
        const size_t r_lo = m0 + mp*32 + i*16 + q, r_hi = r_lo + 8;
#pragma unroll
        for (int j = 0; j < 4; j++) {
            const int col = (half*4 + j)*8 + (lane & 3)*2;
            float2 o0, o1;
            o0.x = silu_f(acc[i*4+j][0]); o0.y = silu_f(acc[i*4+j][1]);
            o1.x = silu_f(acc[i*4+j][2]); o1.y = silu_f(acc[i*4+j][3]);
            *(float2*)&g_xkj2[r_lo*64 + col] = o0;
            *(float2*)&g_xkj2[r_hi*64 + col] = o1;
        }
    }
}

// ---------------- residual block as device fn (A in As, base/ckpt in gmem) -----
__device__ __forceinline__ void do_resid(uint32_t* As,
        const uint32_t* B1f, const float* b1,
        const uint32_t* B2f, const float* b2,
        const float* base, float* ckpt, bool writeAs,
        size_t m0, int mp, int half, int lane) {
    const int q = lane >> 2, sw = q << 2;
    float acc[16][4];

    zero_acc<16>(acc);
    run_mma<128,16,8>(As, B1f, mp, half*8, lane, acc);
    __syncthreads();
    // h = silu(acc + b1) -> As
#pragma unroll
    for (int i = 0; i < 2; i++) {
        const int rl = mp*32 + i*16 + q;
#pragma unroll
        for (int j = 0; j < 8; j++) {
            const int cj = (half*8 + j)*8 + (lane & 3)*2;
            const float2 bj = *(const float2*)&b1[cj];
            float v[4];
            v[0] = silu_f(acc[i*8+j][0] + bj.x);
            v[1] = silu_f(acc[i*8+j][1] + bj.y);
            v[2] = silu_f(acc[i*8+j][2] + bj.x);
            v[3] = silu_f(acc[i*8+j][3] + bj.y);
#pragma unroll
            for (int e = 0; e < 4; e++) {
                const int r = rl + ((e >> 1) ? 8 : 0);
                const int c = cj + (e & 1);
                As[r*128 + (c ^ sw)] = to_tf32(v[e]);
            }
        }
    }
    __syncthreads();

    zero_acc<16>(acc);
    run_mma<128,16,8>(As, B2f, mp, half*8, lane, acc);
    __syncthreads();
    // v = base + silu(acc + b2) -> ckpt gmem [+ As]
#pragma unroll
    for (int i = 0; i < 2; i++) {
        const size_t r_lo = m0 + mp*32 + i*16 + q, r_hi = r_lo + 8;
        const int rl = mp*32 + i*16 + q;
#pragma unroll
        for (int j = 0; j < 8; j++) {
            const int cj = (half*8 + j)*8 + (lane & 3)*2;
            const float2 bj = *(const float2*)&b2[cj];
            const float2 xl = *(const float2*)&base[r_lo*128 + cj];
            const float2 xh = *(const float2*)&base[r_hi*128 + cj];
            float v[4];
            v[0] = xl.x + silu_f(acc[i*8+j][0] + bj.x);
            v[1] = xl.y + silu_f(acc[i*8+j][1] + bj.y);
            v[2] = xh.x + silu_f(acc[i*8+j][2] + bj.x);
            v[3] = xh.y + silu_f(acc[i*8+j][3] + bj.y);
            *(float2*)&ckpt[r_lo*128 + cj] = make_float2(v[0], v[1]);
            *(float2*)&ckpt[r_hi*128 + cj] = make_float2(v[2], v[3]);
            if (writeAs) {
#pragma unroll
                for (int e = 0; e < 4; e++) {
                    const int r = rl + ((e >> 1) ? 8 : 0);
                    const int c = cj + (e & 1);
                    As[r*128 + (c ^ sw)] = to_tf32(v[e]);
                }
            }
        }
    }
    if (writeAs) __syncthreads();
}

// ---------------- TAIL: up + resid_b + final + resid_a0 + resid_a1 -------------
__global__ __launch_bounds__(256, 2)
void tail_kernel(const float* __restrict__ m, const uint32_t* __restrict__ Bf,
                 const float* __restrict__ bb1, const float* __restrict__ bb2,
                 const float* __restrict__ b_final,
                 const float* __restrict__ ba1, const float* __restrict__ ba2,
                 float* __restrict__ out) {
    extern __shared__ __align__(16) uint32_t As[];   // 128*128 u32

    const int tid = threadIdx.x, lane = tid & 31, w = tid >> 5;
    const size_t m0 = (size_t)blockIdx.x * 128;
    const int mp = w >> 1, half = w & 1;
    const int q = lane >> 2, sw = q << 2;

    // stage agg (K=64)
    stage_A<64>(g_agg, m0, As, tid);
    __syncthreads();

    float acc[16][4];

    // ---- GEMM up: upd = x_ji + silu(agg @ W_up) -> g_upd + As ----
    zero_acc<16>(acc);
    run_mma<64,16,8>(As, Bf + OFF_UP, mp, half*8, lane, acc);
    __syncthreads();
#pragma unroll
    for (int i = 0; i < 2; i++) {
        const size_t r_lo = m0 + mp*32 + i*16 + q, r_hi = r_lo + 8;
        const int rl = mp*32 + i*16 + q;
#pragma unroll
        for (int j = 0; j < 8; j++) {
            const int cj = (half*8 + j)*8 + (lane & 3)*2;
            const float2 xl = *(const float2*)&g_xji[r_lo*128 + cj];
            const float2 xh = *(const float2*)&g_xji[r_hi*128 + cj];
            float v[4];
            v[0] = xl.x + silu_f(acc[i*8+j][0]);
            v[1] = xl.y + silu_f(acc[i*8+j][1]);
            v[2] = xh.x + silu_f(acc[i*8+j][2]);
            v[3] = xh.y + silu_f(acc[i*8+j][3]);
            *(float2*)&g_upd[r_lo*128 + cj] = make_float2(v[0], v[1]);
            *(float2*)&g_upd[r_hi*128 + cj] = make_float2(v[2], v[3]);
#pragma unroll
            for (int e = 0; e < 4; e++) {
                const int r = rl + ((e >> 1) ? 8 : 0);
                const int c = cj + (e & 1);
                As[r*128 + (c ^ sw)] = to_tf32(v[e]);
            }
        }
    }
    __syncthreads();

    // ---- residual-before ----
    do_resid(As, Bf + OFF_B1, bb1, Bf + OFF_B2, bb2, g_upd, g_upd, true, m0, mp, half, lane);

    // ---- final: out = m + silu(upd @ W_final + b_final) -> out + As ----
    zero_acc<16>(acc);
    run_mma<128,16,8>(As, Bf + OFF_FIN, mp, half*8, lane, acc);
    __syncthreads();
#pragma unroll
    for (int i = 0; i < 2; i++) {
        const size_t r_lo = m0 + mp*32 + i*16 + q, r_hi = r_lo + 8;
        const int rl = mp*32 + i*16 + q;
#pragma unroll
        for (int j = 0; j < 8; j++) {
            const int cj = (half*8 + j)*8 + (lane & 3)*2;
            const float2 bj = *(const float2*)&b_final[cj];
            const float2 xl = *(const float2*)&m[r_lo*128 + cj];
            const float2 xh = *(const float2*)&m[r_hi*128 + cj];
            float v[4];
            v[0] = xl.x + silu_f(acc[i*8+j][0] + bj.x);
            v[1] = xl.y + silu_f(acc[i*8+j][1] + bj.y);
            v[2] = xh.x + silu_f(acc[i*8+j][2] + bj.x);
            v[3] = xh.y + silu_f(acc[i*8+j][3] + bj.y);
            *(float2*)&out[r_lo*128 + cj] = make_float2(v[0], v[1]);
            *(float2*)&out[r_hi*128 + cj] = make_float2(v[2], v[3]);
#pragma unroll
            for (int e = 0; e < 4; e++) {
                const int r = rl + ((e >> 1) ? 8 : 0);
                const int c = cj + (e & 1);
                As[r*128 + (c ^ sw)] = to_tf32(v[e]);
            }
        }
    }
    __syncthreads();

    // ---- residual-after x2 ----
    do_resid(As, Bf + OFF_A10, ba1,       Bf + OFF_A20, ba2,       out, out, true,  m0, mp, half, lane);
    do_resid(As, Bf + OFF_A11, ba1 + 128, Bf + OFF_A21, ba2 + 128, out, out, false, m0, mp, half, lane);
}

// ---------------- triplet kernel (unchanged, passes) ---------------------------
__global__ __launch_bounds__(256)
void triplet_kernel(const float* __restrict__ sbf,
                    const int* __restrict__ src_idx,
                    const int* __restrict__ dst_idx,
                    const float* __restrict__ W1,
                    const float* __restrict__ W2) {
    __shared__ float sbf_s[16*NSR];
    __shared__ float W1s[NSR*BASIS];
    __shared__ __align__(16) float W2s[BASIS*INT_EMB];
    __shared__ float t8[16][BASIS];

    const int tid = threadIdx.x;
    for (int i = tid; i < NSR*BASIS; i += 256) W1s[i] = W1[i];
    for (int i = tid; i < BASIS*INT_EMB; i += 256) W2s[i] = W2[i];

    const int ngroups = T_TRIP / 16;
    const int half = tid >> 4;
    const int l16  = tid & 15;

    for (int g = blockIdx.x; g < ngroups; g += gridDim.x) {
        const size_t base = (size_t)g * (16*NSR);
        for (int i = tid; i < 16*NSR; i += 256) sbf_s[i] = sbf[base + i];
        __syncthreads();

        if (tid < 128) {
            int tt = tid >> 3, j = tid & 7;
            float s = 0.f;
#pragma unroll
            for (int r = 0; r < NSR; r++) s += sbf_s[tt*NSR + r] * W1s[r*BASIS + j];
            t8[tt][j] = s;
        }
        __syncthreads();

        const int t = g*16 + half;
        const int src = src_idx[t];
        const int dst = dst_idx[t];

        float4 a = {0.f, 0.f, 0.f, 0.f};
#pragma unroll
        for (int j = 0; j < BASIS; j++) {
            const float tv = t8[half][j];
            const float4 w = *(const float4*)&W2s[j*INT_EMB + l16*4];
            a.x += tv*w.x; a.y += tv*w.y; a.z += tv*w.z; a.w += tv*w.w;
        }
        const float4 xk = *(const float4*)(g_xkj2 + (size_t)src*INT_EMB + l16*4);
        a.x *= xk.x; a.y *= xk.y; a.z *= xk.z; a.w *= xk.w;

        atomicAdd((float4*)(g_agg + (size_t)dst*INT_EMB + l16*4), a);
        __syncthreads();
    }
}

// ---------------- host launcher ----------------------------------------------
extern "C" void kernel_launch(void* const* d_in, const int* in_sizes, int n_in,
                              void* d_out, int out_size) {
    const float* m       = (const float*)d_in[0];
    const float* rbf     = (const float*)d_in[1];
    const float* sbf     = (const float*)d_in[2];
    const int*   src_idx = (const int*)d_in[3];
    const int*   dst_idx = (const int*)d_in[4];
    const float* W_rbf1  = (const float*)d_in[5];
    const float* W_rbf2  = (const float*)d_in[6];
    const float* W_sbf1  = (const float*)d_in[7];
    const float* W_sbf2  = (const float*)d_in[8];
    const float* W_ji    = (const float*)d_in[9];
    const float* b_ji    = (const float*)d_in[10];
    const float* W_kj    = (const float*)d_in[11];
    const float* b_kj    = (const float*)d_in[12];
    const float* W_down  = (const float*)d_in[13];
    const float* W_up    = (const float*)d_in[14];
    const float* Wb1     = (const float*)d_in[15];
    const float* bb1     = (const float*)d_in[16];
    const float* Wb2     = (const float*)d_in[17];
    const float* bb2     = (const float*)d_in[18];
    const float* W_final = (const float*)d_in[19];
    const float* b_final = (const float*)d_in[20];
    const float* Wa1     = (const float*)d_in[21];
    const float* ba1     = (const float*)d_in[22];
    const float* Wa2     = (const float*)d_in[23];
    const float* ba2     = (const float*)d_in[24];
    float* out = (float*)d_out;

    uint32_t* p_Bf;
    cudaGetSymbolAddress((void**)&p_Bf, g_Bf);

    const int GB = E_EDGES / 128;     // 2048
    const int SM_K128 = 128*128*4;    // 65536

    cudaFuncSetAttribute((const void*)head_kernel, cudaFuncAttributeMaxDynamicSharedMemorySize, SM_K128);
    cudaFuncSetAttribute((const void*)tail_kernel, cudaFuncAttributeMaxDynamicSharedMemorySize, SM_K128);

    // precompute: fused rbf weight + all B fragments + zero agg
    fuse_wr_kernel<<<3, 256>>>(W_rbf1, W_rbf2);
    zero_agg_kernel<<<(E_EDGES*INT_EMB/4)/256, 256>>>();

    stage_Bg<<<128, 128>>>(W_ji,    p_Bf + OFF_JI,   128, 128);
    stage_Bg<<<128, 128>>>(W_kj,    p_Bf + OFF_KJ,   128, 128);
    stage_Bg<<<64 , 128>>>(W_down,  p_Bf + OFF_DOWN, 128, 64);
    stage_Bg<<<64 , 128>>>(W_up,    p_Bf + OFF_UP,   64 , 128);
    stage_Bg<<<128, 128>>>(Wb1,     p_Bf + OFF_B1,   128, 128);
    stage_Bg<<<128, 128>>>(Wb2,     p_Bf + OFF_B2,   128, 128);
    stage_Bg<<<128, 128>>>(W_final, p_Bf + OFF_FIN,  128, 128);
    stage_Bg<<<128, 128>>>(Wa1,           p_Bf + OFF_A10, 128, 128);
    stage_Bg<<<128, 128>>>(Wa2,           p_Bf + OFF_A20, 128, 128);
    stage_Bg<<<128, 128>>>(Wa1 + 128*128, p_Bf + OFF_A11, 128, 128);
    stage_Bg<<<128, 128>>>(Wa2 + 128*128, p_Bf + OFF_A21, 128, 128);

    // head: x_ji + x_kj2 (3 GEMMs, one staging of m)
    head_kernel<<<GB, 256, SM_K128>>>(m, rbf, p_Bf, b_ji, b_kj);

    // triplet message + segment sum
    triplet_kernel<<<4096, 256>>>(sbf, src_idx, dst_idx, W_sbf1, W_sbf2);

    // tail: up + resid_b + final + resid_a0 + resid_a1 (8 GEMMs, one staging)
    tail_kernel<<<GB, 256, SM_K128>>>(m, p_Bf, bb1, bb2, b_final, ba1, ba2, out);
}

// round 11
// speedup vs baseline: 1.5516x; 1.5516x over previous
#include <cuda_runtime.h>
#include <cstdint>

typedef unsigned long long ull;

#define EMB 128
#define INT_EMB 64
#define NRAD 6
#define NSR 42
#define BASIS 8
#define E_EDGES 262144
#define T_TRIP 2097152

// ---------------- scratch (device globals) ------------------------------------
__device__ float g_Wr[NRAD*EMB];
__device__ float g_xji[(size_t)E_EDGES*EMB];
__device__ float g_tmp[(size_t)E_EDGES*EMB];
__device__ float g_upd[(size_t)E_EDGES*EMB];
__device__ float g_xkj2[(size_t)E_EDGES*INT_EMB];
__device__ float g_agg[(size_t)E_EDGES*INT_EMB];
__device__ uint32_t g_Bf[163840];   // all weights, tf32 fragment layout

// B-frag offsets (u32 elements)
#define OFF_JI   0
#define OFF_KJ   16384
#define OFF_DOWN 32768
#define OFF_UP   40960
#define OFF_B1   49152
#define OFF_B2   65536
#define OFF_FIN  81920
#define OFF_A10  98304
#define OFF_A20  114688
#define OFF_A11  131072
#define OFF_A21  147456

// ---------------- helpers ------------------------------------------------------
__device__ __forceinline__ float silu_f(float x){ return x * (1.0f/(1.0f + __expf(-x))); }
__device__ __forceinline__ uint32_t to_tf32(float f){
    uint32_t u; asm("cvt.rna.tf32.f32 %0, %1;" : "=r"(u) : "f"(f)); return u;
}
__device__ __forceinline__ void mma_tf32(float* c, const uint32_t* a, const uint32_t* b){
    asm volatile("mma.sync.aligned.m16n8k8.row.col.f32.tf32.tf32.f32 "
        "{%0,%1,%2,%3}, {%4,%5,%6,%7}, {%8,%9}, {%0,%1,%2,%3};"
        : "+f"(c[0]), "+f"(c[1]), "+f"(c[2]), "+f"(c[3])
        : "r"(a[0]), "r"(a[1]), "r"(a[2]), "r"(a[3]), "r"(b[0]), "r"(b[1]));
}

// ---------------- K0: fuse W_rbf1 @ W_rbf2 -> g_Wr ----------------------------
__global__ void fuse_wr_kernel(const float* __restrict__ W1, const float* __restrict__ W2) {
    int i = blockIdx.x * blockDim.x + threadIdx.x;
    if (i < NRAD * EMB) {
        int r = i / EMB, n = i % EMB;
        float s = 0.f;
#pragma unroll
        for (int b = 0; b < BASIS; b++) s += W1[r*BASIS + b] * W2[b*EMB + n];
        g_Wr[i] = s;
    }
}

// ---------------- zero g_agg --------------------------------------------------
__global__ void zero_agg_kernel() {
    size_t i = (size_t)blockIdx.x * blockDim.x + threadIdx.x;
    float4 z = {0.f, 0.f, 0.f, 0.f};
    ((float4*)g_agg)[i] = z;
}

// ---------------- B fragment precompute ----------------------------------------
__global__ void stage_Bg(const float* __restrict__ W, uint32_t* __restrict__ out,
                         int K, int N) {
    int i = blockIdx.x * 128 + threadIdx.x;
    int total = K * (N/4);
    if (i >= total) return;
    int k = i / (N/4), n = (i % (N/4)) * 4;
    const float4 b4 = *(const float4*)&W[(size_t)k*N + n];
    float v[4] = {b4.x, b4.y, b4.z, b4.w};
    int NT = N/8;
    int s = k >> 3, kk = k & 7, rg = kk >> 2;
#pragma unroll
    for (int e = 0; e < 4; e++) {
        int nn = (n+e) & 7, nt = (n+e) >> 3;
        int ln = (nn << 2) | (kk & 3);
        out[((s*NT + nt)*32 + ln)*2 + rg] = to_tf32(v[e]);
    }
}

// ---------------- A staging: row-major, XOR-swizzled, tf32 --------------------
template<int K>
__device__ __forceinline__ void stage_A(const float* __restrict__ A, size_t m0,
                                        uint32_t* __restrict__ As, int tid) {
    constexpr int QPR = K/4;
    for (int i = tid; i < 128*QPR; i += 256) {
        int row = i / QPR, q = i % QPR;
        const float4 a4 = *(const float4*)&A[(m0+row)*K + q*4];
        uint4 t;
        t.x = to_tf32(a4.x); t.y = to_tf32(a4.y); t.z = to_tf32(a4.z); t.w = to_tf32(a4.w);
        int c = (q*4) ^ ((row & 7) << 2);
        *(uint4*)&As[row*K + c] = t;
    }
}

// ---------------- generic fused GEMM (tf32 mma.sync, WMT=2 x WNT=NT/2) ---------
// out = [res +] silu(A@W [+ bias]) [* rbf_env]
// Warp grid 4(m) x 2(n): warp owns 32 rows x N/2 cols.  (R6, best config)
template<int N, int K, bool MUL_RBF, bool ADD_RES>
__global__ __launch_bounds__(256, 2)
void gemm_mma3(const float* __restrict__ A, const uint32_t* __restrict__ Bf,
               const float* __restrict__ bias, const float* __restrict__ res,
               const float* __restrict__ rbf, float* __restrict__ out) {
    constexpr int KS = K/8, NT = N/8, WNT = NT/2;
    extern __shared__ __align__(16) uint32_t As[];
    __shared__ float s_Wr[MUL_RBF ? NRAD*EMB : 1];

    const int tid = threadIdx.x, lane = tid & 31, w = tid >> 5;
    const size_t m0 = (size_t)blockIdx.x * 128;
    const int mp = w >> 1;
    const int nt0 = (w & 1) * WNT;

    if (MUL_RBF) for (int i = tid; i < NRAD*EMB; i += 256) s_Wr[i] = g_Wr[i];
    stage_A<K>(A, m0, As, tid);
    __syncthreads();

    float acc[2][WNT][4];
#pragma unroll
    for (int i = 0; i < 2; i++)
#pragma unroll
        for (int j = 0; j < WNT; j++)
#pragma unroll
            for (int e = 0; e < 4; e++) acc[i][j][e] = 0.f;

    const int q = lane >> 2;
    const int sw = q << 2;
    const int rowA0 = (mp*32 + q) * K;
    const int rowA1 = (mp*32 + 16 + q) * K;

#pragma unroll
    for (int s = 0; s < KS; s++) {
        const int c0 = s*8 + (lane & 3);
        uint32_t a[2][4];
        a[0][0] = As[rowA0       + (c0 ^ sw)];
        a[0][1] = As[rowA0 + 8*K + (c0 ^ sw)];
        a[0][2] = As[rowA0       + ((c0+4) ^ sw)];
        a[0][3] = As[rowA0 + 8*K + ((c0+4) ^ sw)];
        a[1][0] = As[rowA1       + (c0 ^ sw)];
        a[1][1] = As[rowA1 + 8*K + (c0 ^ sw)];
        a[1][2] = As[rowA1       + ((c0+4) ^ sw)];
        a[1][3] = As[rowA1 + 8*K + ((c0+4) ^ sw)];
#pragma unroll
        for (int j = 0; j < WNT; j++) {
            uint2 b = *(const uint2*)&Bf[((s*NT + nt0 + j)*32 + lane)*2];
            mma_tf32(acc[0][j], a[0], (const uint32_t*)&b);
            mma_tf32(acc[1][j], a[1], (const uint32_t*)&b);
        }
    }

    // epilogue
#pragma unroll
    for (int i = 0; i < 2; i++) {
        const size_t r_lo = m0 + mp*32 + i*16 + q;
        const size_t r_hi = r_lo + 8;
        float r6lo[NRAD], r6hi[NRAD];
        if (MUL_RBF) {
#pragma unroll
            for (int l = 0; l < NRAD; l++) { r6lo[l] = rbf[r_lo*NRAD + l]; r6hi[l] = rbf[r_hi*NRAD + l]; }
        }
#pragma unroll
        for (int j = 0; j < WNT; j++) {
            const int col = (nt0 + j)*8 + (lane & 3)*2;
            float2 bj = make_float2(0.f, 0.f);
            if (bias) bj = *(const float2*)&bias[col];
            float v00 = silu_f(acc[i][j][0] + bj.x);
            float v01 = silu_f(acc[i][j][1] + bj.y);
            float v10 = silu_f(acc[i][j][2] + bj.x);
            float v11 = silu_f(acc[i][j][3] + bj.y);
            if (MUL_RBF) {
                float e00=0.f,e01=0.f,e10=0.f,e11=0.f;
#pragma unroll
                for (int l = 0; l < NRAD; l++) {
                    const float w0 = s_Wr[l*EMB + col], w1 = s_Wr[l*EMB + col + 1];
                    e00 += r6lo[l]*w0; e01 += r6lo[l]*w1;
                    e10 += r6hi[l]*w0; e11 += r6hi[l]*w1;
                }
                v00 *= e00; v01 *= e01; v10 *= e10; v11 *= e11;
            }
            if (ADD_RES) {
                const float2 rl = *(const float2*)&res[r_lo*N + col];
                const float2 rh = *(const float2*)&res[r_hi*N + col];
                v00 += rl.x; v01 += rl.y; v10 += rh.x; v11 += rh.y;
            }
            float2 o0; o0.x = v00; o0.y = v01;
            float2 o1; o1.x = v10; o1.y = v11;
            *(float2*)&out[r_lo*N + col] = o0;
            *(float2*)&out[r_hi*N + col] = o1;
        }
    }
}

// ---------------- fused ji+kj kernel: same A tile, two B's, two epilogues ------
// x_ji = silu(m@W_ji + b_ji);  tmp = silu(m@W_kj + b_kj) * rbf_env
// No As rewrite between phases (A = m for both); acc dead between phases.
__global__ __launch_bounds__(256, 2)
void gemm2_mma3(const float* __restrict__ m,
                const uint32_t* __restrict__ Bf_ji, const uint32_t* __restrict__ Bf_kj,
                const float* __restrict__ b_ji, const float* __restrict__ b_kj,
                const float* __restrict__ rbf,
                float* __restrict__ out_ji, float* __restrict__ out_kj) {
    constexpr int KS = 16, NT = 16, WNT = 8;
    extern __shared__ __align__(16) uint32_t As[];
    __shared__ float s_Wr[NRAD*EMB];

    const int tid = threadIdx.x, lane = tid & 31, w = tid >> 5;
    const size_t m0 = (size_t)blockIdx.x * 128;
    const int mp = w >> 1;
    const int nt0 = (w & 1) * WNT;

    for (int i = tid; i < NRAD*EMB; i += 256) s_Wr[i] = g_Wr[i];
    stage_A<128>(m, m0, As, tid);
    __syncthreads();

    const int q = lane >> 2;
    const int sw = q << 2;
    const int rowA0 = (mp*32 + q) * 128;
    const int rowA1 = (mp*32 + 16 + q) * 128;

    float acc[2][WNT][4];

    // ======== phase 1: x_ji ========
#pragma unroll
    for (int i = 0; i < 2; i++)
#pragma unroll
        for (int j = 0; j < WNT; j++)
#pragma unroll
            for (int e = 0; e < 4; e++) acc[i][j][e] = 0.f;
#pragma unroll
    for (int s = 0; s < KS; s++) {
        const int c0 = s*8 + (lane & 3);
        uint32_t a[2][4];
        a[0][0] = As[rowA0         + (c0 ^ sw)];
        a[0][1] = As[rowA0 + 8*128 + (c0 ^ sw)];
        a[0][2] = As[rowA0         + ((c0+4) ^ sw)];
        a[0][3] = As[rowA0 + 8*128 + ((c0+4) ^ sw)];
        a[1][0] = As[rowA1         + (c0 ^ sw)];
        a[1][1] = As[rowA1 + 8*128 + (c0 ^ sw)];
        a[1][2] = As[rowA1         + ((c0+4) ^ sw)];
        a[1][3] = As[rowA1 + 8*128 + ((c0+4) ^ sw)];
#pragma unroll
        for (int j = 0; j < WNT; j++) {
            uint2 b = *(const uint2*)&Bf_ji[((s*NT + nt0 + j)*32 + lane)*2];
            mma_tf32(acc[0][j], a[0], (const uint32_t*)&b);
            mma_tf32(acc[1][j], a[1], (const uint32_t*)&b);
        }
    }
#pragma unroll
    for (int i = 0; i < 2; i++) {
        const size_t r_lo = m0 + mp*32 + i*16 + q;
        const size_t r_hi = r_lo + 8;
#pragma unroll
        for (int j = 0; j < WNT; j++) {
            const int col = (nt0 + j)*8 + (lane & 3)*2;
            const float2 bj = *(const float2*)&b_ji[col];
            float2 o0, o1;
            o0.x = silu_f(acc[i][j][0] + bj.x);
            o0.y = silu_f(acc[i][j][1] + bj.y);
            o1.x = silu_f(acc[i][j][2] + bj.x);
            o1.y = silu_f(acc[i][j][3] + bj.y);
            *(float2*)&out_ji[r_lo*128 + col] = o0;
            *(float2*)&out_ji[r_hi*128 + col] = o1;
        }
    }

    // ======== phase 2: tmp (kj * rbf_env) ========
#pragma unroll
    for (int i = 0; i < 2; i++)
#pragma unroll
        for (int j = 0; j < WNT; j++)
#pragma unroll
            for (int e = 0; e < 4; e++) acc[i][j][e] = 0.f;
#pragma unroll
    for (int s = 0; s < KS; s++) {
        const int c0 = s*8 + (lane & 3);
        uint32_t a[2][4];
        a[0][0] = As[rowA0         + (c0 ^ sw)];
        a[0][1] = As[rowA0 + 8*128 + (c0 ^ sw)];
        a[0][2] = As[rowA0         + ((c0+4) ^ sw)];
        a[0][3] = As[rowA0 + 8*128 + ((c0+4) ^ sw)];
        a[1][0] = As[rowA1         + (c0 ^ sw)];
        a[1][1] = As[rowA1 + 8*128 + (c0 ^ sw)];
        a[1][2] = As[rowA1         + ((c0+4) ^ sw)];
        a[1][3] = As[rowA1 + 8*128 + ((c0+4) ^ sw)];
#pragma unroll
        for (int j = 0; j < WNT; j++) {
            uint2 b = *(const uint2*)&Bf_kj[((s*NT + nt0 + j)*32 + lane)*2];
            mma_tf32(acc[0][j], a[0], (const uint32_t*)&b);
            mma_tf32(acc[1][j], a[1], (const uint32_t*)&b);
        }
    }
#pragma unroll
    for (int i = 0; i < 2; i++) {
        const size_t r_lo = m0 + mp*32 + i*16 + q;
        const size_t r_hi = r_lo + 8;
        float r6lo[NRAD], r6hi[NRAD];
#pragma unroll
        for (int l = 0; l < NRAD; l++) { r6lo[l] = rbf[r_lo*NRAD + l]; r6hi[l] = rbf[r_hi*NRAD + l]; }
#pragma unroll
        for (int j = 0; j < WNT; j++) {
            const int col = (nt0 + j)*8 + (lane & 3)*2;
            const float2 bj = *(const float2*)&b_kj[col];
            float e00=0.f,e01=0.f,e10=0.f,e11=0.f;
#pragma unroll
            for (int l = 0; l < NRAD; l++) {
                const float w0 = s_Wr[l*EMB + col], w1 = s_Wr[l*EMB + col + 1];
                e00 += r6lo[l]*w0; e01 += r6lo[l]*w1;
                e10 += r6hi[l]*w0; e11 += r6hi[l]*w1;
            }
            float2 o0, o1;
            o0.x = silu_f(acc[i][j][0] + bj.x) * e00;
            o0.y = silu_f(acc[i][j][1] + bj.y) * e01;
            o1.x = silu_f(acc[i][j][2] + bj.x) * e10;
            o1.y = silu_f(acc[i][j][3] + bj.y) * e11;
            *(float2*)&out_kj[r_lo*128 + col] = o0;
            *(float2*)&out_kj[r_hi*128 + col] = o1;
        }
    }
}

// ---------------- fused residual block: out = x + silu(silu(x@W1+b1)@W2+b2) ----
__global__ __launch_bounds__(256, 2)
void resid_mma3(const float* __restrict__ X,
                const uint32_t* __restrict__ B1f, const float* __restrict__ b1,
                const uint32_t* __restrict__ B2f, const float* __restrict__ b2,
                float* __restrict__ out) {
    constexpr int KS = 16, NT = 16, WNT = 8;
    extern __shared__ __align__(16) uint32_t As[];

    const int tid = threadIdx.x, lane = tid & 31, w = tid >> 5;
    const size_t m0 = (size_t)blockIdx.x * 128;
    const int mp = w >> 1;
    const int nt0 = (w & 1) * WNT;

    stage_A<128>(X, m0, As, tid);
    __syncthreads();

    const int q = lane >> 2;
    const int sw = q << 2;
    const int rowA0 = (mp*32 + q) * 128;
    const int rowA1 = (mp*32 + 16 + q) * 128;

    float acc[2][WNT][4];
#pragma unroll
    for (int i = 0; i < 2; i++)
#pragma unroll
        for (int j = 0; j < WNT; j++)
#pragma unroll
            for (int e = 0; e < 4; e++) acc[i][j][e] = 0.f;

    // ---- GEMM1: acc = X @ W1 ----
#pragma unroll
    for (int s = 0; s < KS; s++) {
        const int c0 = s*8 + (lane & 3);
        uint32_t a[2][4];
        a[0][0] = As[rowA0         + (c0 ^ sw)];
        a[0][1] = As[rowA0 + 8*128 + (c0 ^ sw)];
        a[0][2] = As[rowA0         + ((c0+4) ^ sw)];
        a[0][3] = As[rowA0 + 8*128 + ((c0+4) ^ sw)];
        a[1][0] = As[rowA1         + (c0 ^ sw)];
        a[1][1] = As[rowA1 + 8*128 + (c0 ^ sw)];
        a[1][2] = As[rowA1         + ((c0+4) ^ sw)];
        a[1][3] = As[rowA1 + 8*128 + ((c0+4) ^ sw)];
#pragma unroll
        for (int j = 0; j < WNT; j++) {
            uint2 b = *(const uint2*)&B1f[((s*NT + nt0 + j)*32 + lane)*2];
            mma_tf32(acc[0][j], a[0], (const uint32_t*)&b);
            mma_tf32(acc[1][j], a[1], (const uint32_t*)&b);
        }
    }
    __syncthreads();

    // ---- epilogue1: h = silu(acc + b1) -> back into As ----
#pragma unroll
    for (int i = 0; i < 2; i++) {
        const int rl = mp*32 + i*16 + q;
#pragma unroll
        for (int j = 0; j < WNT; j++) {
            const int cj = (nt0 + j)*8 + (lane & 3)*2;
            const float2 bj = *(const float2*)&b1[cj];
            float v[4];
            v[0] = silu_f(acc[i][j][0] + bj.x);
            v[1] = silu_f(acc[i][j][1] + bj.y);
            v[2] = silu_f(acc[i][j][2] + bj.x);
            v[3] = silu_f(acc[i][j][3] + bj.y);
#pragma unroll
            for (int e = 0; e < 4; e++) {
                const int r = rl + ((e >> 1) ? 8 : 0);
                const int c = cj + (e & 1);
                As[r*128 + (c ^ sw)] = to_tf32(v[e]);
            }
        }
    }
    __syncthreads();

    // ---- GEMM2: acc = h @ W2 ----
#pragma unroll
    for (int i = 0; i < 2; i++)
#pragma unroll
        for (int j = 0; j < WNT; j++)
#pragma unroll
            for (int e = 0; e < 4; e++) acc[i][j][e] = 0.f;
#pragma unroll
    for (int s = 0; s < KS; s++) {
        const int c0 = s*8 + (lane & 3);
        uint32_t a[2][4];
        a[0][0] = As[rowA0         + (c0 ^ sw)];
        a[0][1] = As[rowA0 + 8*128 + (c0 ^ sw)];
        a[0][2] = As[rowA0         + ((c0+4) ^ sw)];
        a[0][3] = As[rowA0 + 8*128 + ((c0+4) ^ sw)];
        a[1][0] = As[rowA1         + (c0 ^ sw)];
        a[1][1] = As[rowA1 + 8*128 + (c0 ^ sw)];
        a[1][2] = As[rowA1         + ((c0+4) ^ sw)];
        a[1][3] = As[rowA1 + 8*128 + ((c0+4) ^ sw)];
#pragma unroll
        for (int j = 0; j < WNT; j++) {
            uint2 b = *(const uint2*)&B2f[((s*NT + nt0 + j)*32 + lane)*2];
            mma_tf32(acc[0][j], a[0], (const uint32_t*)&b);
            mma_tf32(acc[1][j], a[1], (const uint32_t*)&b);
        }
    }

    // ---- epilogue2: out = X + silu(acc + b2) ----
#pragma unroll
    for (int i = 0; i < 2; i++) {
        const size_t r_lo = m0 + mp*32 + i*16 + q;
        const size_t r_hi = r_lo + 8;
#pragma unroll
        for (int j = 0; j < WNT; j++) {
            const int col = (nt0 + j)*8 + (lane & 3)*2;
            const float2 bj = *(const float2*)&b2[col];
            const float2 xl = *(const float2*)&X[r_lo*128 + col];
            const float2 xh = *(const float2*)&X[r_hi*128 + col];
            float2 o0, o1;
            o0.x = xl.x + silu_f(acc[i][j][0] + bj.x);
            o0.y = xl.y + silu_f(acc[i][j][1] + bj.y);
            o1.x = xh.x + silu_f(acc[i][j][2] + bj.x);
            o1.y = xh.y + silu_f(acc[i][j][3] + bj.y);
            *(float2*)&out[r_lo*128 + col] = o0;
            *(float2*)&out[r_hi*128 + col] = o1;
        }
    }
}

// ---------------- triplet kernel (unchanged, passes) ---------------------------
__global__ __launch_bounds__(256)
void triplet_kernel(const float* __restrict__ sbf,
                    const int* __restrict__ src_idx,
                    const int* __restrict__ dst_idx,
                    const float* __restrict__ W1,
                    const float* __restrict__ W2) {
    __shared__ float sbf_s[16*NSR];
    __shared__ float W1s[NSR*BASIS];
    __shared__ __align__(16) float W2s[BASIS*INT_EMB];
    __shared__ float t8[16][BASIS];

    const int tid = threadIdx.x;
    for (int i = tid; i < NSR*BASIS; i += 256) W1s[i] = W1[i];
    for (int i = tid; i < BASIS*INT_EMB; i += 256) W2s[i] = W2[i];

    const int ngroups = T_TRIP / 16;
    const int half = tid >> 4;
    const int l16  = tid & 15;

    for (int g = blockIdx.x; g < ngroups; g += gridDim.x) {
        const size_t base = (size_t)g * (16*NSR);
        for (int i = tid; i < 16*NSR; i += 256) sbf_s[i] = sbf[base + i];
        __syncthreads();

        if (tid < 128) {
            int tt = tid >> 3, j = tid & 7;
            float s = 0.f;
#pragma unroll
            for (int r = 0; r < NSR; r++) s += sbf_s[tt*NSR + r] * W1s[r*BASIS + j];
            t8[tt][j] = s;
        }
        __syncthreads();

        const int t = g*16 + half;
        const int src = src_idx[t];
        const int dst = dst_idx[t];

        float4 a = {0.f, 0.f, 0.f, 0.f};
#pragma unroll
        for (int j = 0; j < BASIS; j++) {
            const float tv = t8[half][j];
            const float4 w = *(const float4*)&W2s[j*INT_EMB + l16*4];
            a.x += tv*w.x; a.y += tv*w.y; a.z += tv*w.z; a.w += tv*w.w;
        }
        const float4 xk = *(const float4*)(g_xkj2 + (size_t)src*INT_EMB + l16*4);
        a.x *= xk.x; a.y *= xk.y; a.z *= xk.z; a.w *= xk.w;

        atomicAdd((float4*)(g_agg + (size_t)dst*INT_EMB + l16*4), a);
        __syncthreads();
    }
}

// ---------------- host launcher ----------------------------------------------
extern "C" void kernel_launch(void* const* d_in, const int* in_sizes, int n_in,
                              void* d_out, int out_size) {
    const float* m       = (const float*)d_in[0];
    const float* rbf     = (const float*)d_in[1];
    const float* sbf     = (const float*)d_in[2];
    const int*   src_idx = (const int*)d_in[3];
    const int*   dst_idx = (const int*)d_in[4];
    const float* W_rbf1  = (const float*)d_in[5];
    const float* W_rbf2  = (const float*)d_in[6];
    const float* W_sbf1  = (const float*)d_in[7];
    const float* W_sbf2  = (const float*)d_in[8];
    const float* W_ji    = (const float*)d_in[9];
    const float* b_ji    = (const float*)d_in[10];
    const float* W_kj    = (const float*)d_in[11];
    const float* b_kj    = (const float*)d_in[12];
    const float* W_down  = (const float*)d_in[13];
    const float* W_up    = (const float*)d_in[14];
    const float* Wb1     = (const float*)d_in[15];
    const float* bb1     = (const float*)d_in[16];
    const float* Wb2     = (const float*)d_in[17];
    const float* bb2     = (const float*)d_in[18];
    const float* W_final = (const float*)d_in[19];
    const float* b_final = (const float*)d_in[20];
    const float* Wa1     = (const float*)d_in[21];
    const float* ba1     = (const float*)d_in[22];
    const float* Wa2     = (const float*)d_in[23];
    const float* ba2     = (const float*)d_in[24];
    float* out = (float*)d_out;

    float *p_xji, *p_tmp, *p_upd, *p_xkj2, *p_agg;
    uint32_t* p_Bf;
    cudaGetSymbolAddress((void**)&p_xji,  g_xji);
    cudaGetSymbolAddress((void**)&p_tmp,  g_tmp);
    cudaGetSymbolAddress((void**)&p_upd,  g_upd);
    cudaGetSymbolAddress((void**)&p_xkj2, g_xkj2);
    cudaGetSymbolAddress((void**)&p_agg,  g_agg);
    cudaGetSymbolAddress((void**)&p_Bf,   g_Bf);

    const int GB = E_EDGES / 128;     // 2048
    const int SM_K128 = 128*128*4;    // 65536
    const int SM_K64  = 128*64*4;     // 32768

    cudaFuncSetAttribute((const void*)gemm2_mma3, cudaFuncAttributeMaxDynamicSharedMemorySize, SM_K128);
    cudaFuncSetAttribute((const void*)gemm_mma3<128,128,false,true >, cudaFuncAttributeMaxDynamicSharedMemorySize, SM_K128);
    cudaFuncSetAttribute((const void*)gemm_mma3<64 ,128,false,false>, cudaFuncAttributeMaxDynamicSharedMemorySize, SM_K128);
    cudaFuncSetAttribute((const void*)gemm_mma3<128,64 ,false,true >, cudaFuncAttributeMaxDynamicSharedMemorySize, SM_K64);
    cudaFuncSetAttribute((const void*)resid_mma3, cudaFuncAttributeMaxDynamicSharedMemorySize, SM_K128);

    // ---- launch order arranged so launch #6 (ncu -s 5 -c 1) = gemm2_mma3 ----
    stage_Bg<<<128, 128>>>(W_ji, p_Bf + OFF_JI, 128, 128);            // 1
    stage_Bg<<<128, 128>>>(W_kj, p_Bf + OFF_KJ, 128, 128);            // 2
    fuse_wr_kernel<<<3, 256>>>(W_rbf1, W_rbf2);                       // 3
    zero_agg_kernel<<<(E_EDGES*INT_EMB/4)/256, 256>>>();              // 4
    stage_Bg<<<64 , 128>>>(W_down, p_Bf + OFF_DOWN, 128, 64);         // 5

    // x_ji & tmp in one pass (shared A staging)                      // 6 <- profiled
    gemm2_mma3<<<GB,256,SM_K128>>>(m, p_Bf + OFF_JI, p_Bf + OFF_KJ,
                                   b_ji, b_kj, rbf, p_xji, p_tmp);

    // remaining weight staging
    stage_Bg<<<64 , 128>>>(W_up,    p_Bf + OFF_UP,   64 , 128);
    stage_Bg<<<128, 128>>>(Wb1,     p_Bf + OFF_B1,   128, 128);
    stage_Bg<<<128, 128>>>(Wb2,     p_Bf + OFF_B2,   128, 128);
    stage_Bg<<<128, 128>>>(W_final, p_Bf + OFF_FIN,  128, 128);
    stage_Bg<<<128, 128>>>(Wa1,           p_Bf + OFF_A10, 128, 128);
    stage_Bg<<<128, 128>>>(Wa2,           p_Bf + OFF_A20, 128, 128);
    stage_Bg<<<128, 128>>>(Wa1 + 128*128, p_Bf + OFF_A11, 128, 128);
    stage_Bg<<<128, 128>>>(Wa2 + 128*128, p_Bf + OFF_A21, 128, 128);

    // x_kj2 = silu(tmp @ W_down)
    gemm_mma3<64 ,128,false,false><<<GB,256,SM_K128>>>(p_tmp, p_Bf + OFF_DOWN, nullptr, nullptr, nullptr, p_xkj2);

    // triplet message + segment sum
    triplet_kernel<<<4096, 256>>>(sbf, src_idx, dst_idx, W_sbf1, W_sbf2);

    // upd = x_ji + silu(agg @ W_up)
    gemm_mma3<128,64 ,false,true ><<<GB,256,SM_K64>>>(p_agg, p_Bf + OFF_UP, nullptr, p_xji, nullptr, p_upd);
    // residual-before (N_BEFORE=1), in-place
    resid_mma3<<<GB,256,SM_K128>>>(p_upd, p_Bf + OFF_B1, bb1, p_Bf + OFF_B2, bb2, p_upd);
    // final: out = m + silu(upd @ W_final + b_final)
    gemm_mma3<128,128,false,true ><<<GB,256,SM_K128>>>(p_upd, p_Bf + OFF_FIN, b_final, m, nullptr, out);
    // residual-after (N_AFTER=2), in-place on out
    resid_mma3<<<GB,256,SM_K128>>>(out, p_Bf + OFF_A10, ba1,       p_Bf + OFF_A20, ba2,       out);
    resid_mma3<<<GB,256,SM_K128>>>(out, p_Bf + OFF_A11, ba1 + 128, p_Bf + OFF_A21, ba2 + 128, out);
}